// round 13
// baseline (speedup 1.0000x reference)
#include <cuda_runtime.h>
#include <cstdint>

#define EDIM    8
#define NCODES  1024
#define HPAIR   256          // pairs per codebook half
#define SP      32768        // 32*32*32 spatial per batch
#define THREADS 128
#define QPT     3            // queries per thread (blocked)
#define NVEC    262144
#define NZ      (NVEC * EDIM)
#define NCHUNK  683          // ceil(NVEC / (THREADS*QPT))

typedef unsigned long long ull;

// ---- device scratch (no allocations; self-resetting across graph replays) ----
__device__ float    g_bd[2 * NVEC];    // best dist per (half, query)
__device__ int      g_bi[2 * NVEC];    // best code idx per (half, query)
__device__ float    g_partial[NCHUNK]; // per-chunk loss partials
__device__ int      g_used[NCODES];    // set by merger, counted+reset by finalizer
__device__ unsigned g_ct[NCHUNK];      // per-chunk tickets (merger resets)
__device__ unsigned g_ticket = 0;      // global ticket; finalizer resets

// ---- packed f32x2 helpers (Blackwell FFMA2 path, PTX-only) ----
__device__ __forceinline__ ull pack2(float lo, float hi){
    ull d;
    asm("mov.b64 %0, {%1, %2};" : "=l"(d)
        : "r"(__float_as_uint(lo)), "r"(__float_as_uint(hi)));
    return d;
}
__device__ __forceinline__ ull fma2(ull a, ull b, ull c){
    ull d; asm("fma.rn.f32x2 %0, %1, %2, %3;" : "=l"(d) : "l"(a), "l"(b), "l"(c));
    return d;
}
__device__ __forceinline__ ull mul2(ull a, ull b){
    ull d; asm("mul.rn.f32x2 %0, %1, %2;" : "=l"(d) : "l"(a), "l"(b));
    return d;
}
__device__ __forceinline__ ull add2(ull a, ull b){
    ull d; asm("add.rn.f32x2 %0, %1, %2;" : "=l"(d) : "l"(a), "l"(b));
    return d;
}
union U64F2 { ull u; float2 f; };
__device__ __forceinline__ float2 asf2(ull v){ U64F2 x; x.u = v; return x.f; }

// Bit-exact pair distance: d_pair = fma2(dot2, {-2,-2}, add2(ee2, zz2))
// (this exact op structure reproduces the reference's rounding; do not change)
__device__ __forceinline__ ull pair_dist(const ulonglong2* ep, ull eep,
                                         const ull* zp, ull zzp, ull m2){
    const ulonglong2 e01 = ep[0];
    const ulonglong2 e23 = ep[1];
    const ulonglong2 e45 = ep[2];
    const ulonglong2 e67 = ep[3];
    ull a = mul2(zp[0], e01.x);
    a = fma2(zp[1], e01.y, a);
    a = fma2(zp[2], e23.x, a);
    a = fma2(zp[3], e23.y, a);
    a = fma2(zp[4], e45.x, a);
    a = fma2(zp[5], e45.y, a);
    a = fma2(zp[6], e67.x, a);
    a = fma2(zp[7], e67.y, a);
    return fma2(a, m2, add2(eep, zzp));
}

// ---- one kernel: half-codebook search + chunk-ticket merge + global finalize ----
__global__ __launch_bounds__(THREADS, 6) void vq_main(
    const float* __restrict__ z,
    const float* __restrict__ emb,
    float* __restrict__ out,
    int nctas)
{
    __shared__ __align__(16) float2 sE[HPAIR * EDIM];  // half codebook, 16KB
    __shared__ __align__(16) float  sEE[HPAIR * 2];    // half norms, 2KB
    __shared__ float sRed[THREADS / 32];
    __shared__ bool  sMerge, sLast;

    const int tid   = threadIdx.x;
    const int h     = blockIdx.x & 1;        // codebook half
    const int chunk = blockIdx.x >> 1;       // query chunk
    const int pbase = h * HPAIR;             // first global pair of this half

    // Stage this half's codebook with float4 loads; norms fused (no 2nd gmem pass).
    // Thread handles 2 pairs: pairs tid and tid+128.
    #pragma unroll
    for (int r = 0; r < 2; r++){
        const int p = tid + r * THREADS;     // local pair 0..255
        const int P = pbase + p;
        const float4* c4 = reinterpret_cast<const float4*>(emb + (size_t)(2*P) * EDIM);
        const float4 a0 = c4[0], a1 = c4[1]; // code 2P
        const float4 b0 = c4[2], b1 = c4[3]; // code 2P+1
        float2* se = sE + p * EDIM;
        se[0] = make_float2(a0.x, b0.x); se[1] = make_float2(a0.y, b0.y);
        se[2] = make_float2(a0.z, b0.z); se[3] = make_float2(a0.w, b0.w);
        se[4] = make_float2(a1.x, b1.x); se[5] = make_float2(a1.y, b1.y);
        se[6] = make_float2(a1.z, b1.z); se[7] = make_float2(a1.w, b1.w);
        float sa = a0.x*a0.x; sa = fmaf(a0.y,a0.y,sa); sa = fmaf(a0.z,a0.z,sa);
        sa = fmaf(a0.w,a0.w,sa); sa = fmaf(a1.x,a1.x,sa); sa = fmaf(a1.y,a1.y,sa);
        sa = fmaf(a1.z,a1.z,sa); sa = fmaf(a1.w,a1.w,sa);
        float sb = b0.x*b0.x; sb = fmaf(b0.y,b0.y,sb); sb = fmaf(b0.z,b0.z,sb);
        sb = fmaf(b0.w,b0.w,sb); sb = fmaf(b1.x,b1.x,sb); sb = fmaf(b1.y,b1.y,sb);
        sb = fmaf(b1.z,b1.z,sb); sb = fmaf(b1.w,b1.w,sb);
        sEE[2*p]   = sa;
        sEE[2*p+1] = sb;
    }
    __syncthreads();

    // Blocked query mapping: this thread owns queries base..base+2 (guarded).
    const int base = (chunk * THREADS + tid) * QPT;

    int  nq[QPT];
    bool vq[QPT];
    ull  zp[QPT][EDIM];
    ull  zzp[QPT];

    #pragma unroll
    for (int q = 0; q < QPT; q++){
        nq[q] = base + q;
        vq[q] = nq[q] < NVEC;
        float zz = 0.f;
        if (vq[q]){
            const int b = nq[q] >> 15;
            const int s = nq[q] & (SP - 1);
            const float* zptr = z + (size_t)b * (EDIM * SP) + s;
            #pragma unroll
            for (int c = 0; c < EDIM; c++){
                float v = zptr[c * SP];
                zp[q][c] = pack2(v, v);
                zz = fmaf(v, v, zz);
            }
        } else {
            #pragma unroll
            for (int c = 0; c < EDIM; c++) zp[q][c] = 0ull;
        }
        zzp[q] = pack2(zz, zz);
    }
    const ull m2 = pack2(-2.f, -2.f);

    float best[QPT];
    int   bgp[QPT];                            // winning LOCAL group base pair (even)
    #pragma unroll
    for (int q = 0; q < QPT; q++){ best[q] = 3.4e38f; bgp[q] = 0; }

    // Group of 2 pairs per step; codebook loads amortized over 3 queries.
    for (int p = 0; p < HPAIR; p += 2){
        const ulonglong2* epA = reinterpret_cast<const ulonglong2*>(sE + p * EDIM);
        const ulonglong2* epB = reinterpret_cast<const ulonglong2*>(sE + (p + 1) * EDIM);
        const ulonglong2 eeAB = *reinterpret_cast<const ulonglong2*>(sEE + 2 * p);

        float2 dA0 = asf2(pair_dist(epA, eeAB.x, zp[0], zzp[0], m2));
        float2 dA1 = asf2(pair_dist(epA, eeAB.x, zp[1], zzp[1], m2));
        float2 dA2 = asf2(pair_dist(epA, eeAB.x, zp[2], zzp[2], m2));
        float2 dB0 = asf2(pair_dist(epB, eeAB.y, zp[0], zzp[0], m2));
        float2 dB1 = asf2(pair_dist(epB, eeAB.y, zp[1], zzp[1], m2));
        float2 dB2 = asf2(pair_dist(epB, eeAB.y, zp[2], zzp[2], m2));

        {
            float gm = fminf(fminf(dA0.x, dA0.y), fminf(dB0.x, dB0.y));
            bool u = gm < best[0]; bgp[0] = u ? p : bgp[0]; best[0] = fminf(best[0], gm);
        }
        {
            float gm = fminf(fminf(dA1.x, dA1.y), fminf(dB1.x, dB1.y));
            bool u = gm < best[1]; bgp[1] = u ? p : bgp[1]; best[1] = fminf(best[1], gm);
        }
        {
            float gm = fminf(fminf(dA2.x, dA2.y), fminf(dB2.x, dB2.y));
            bool u = gm < best[2]; bgp[2] = u ? p : bgp[2]; best[2] = fminf(best[2], gm);
        }
    }

    // Rescan winning 2-pair group (bit-exact), first-occurrence argmin; store.
    #pragma unroll
    for (int q = 0; q < QPT; q++){
        if (!vq[q]) continue;
        const int gp = bgp[q];
        float bd = 3.4e38f;
        int bi = 0;
        #pragma unroll
        for (int j = 0; j < 2; j++){
            const int p = gp + j;
            const ulonglong2* ep = reinterpret_cast<const ulonglong2*>(sE + p * EDIM);
            const ull eep = *reinterpret_cast<const ull*>(sEE + 2 * p);
            float2 df = asf2(pair_dist(ep, eep, zp[q], zzp[q], m2));
            if (df.x < bd){ bd = df.x; bi = 2*(pbase + p); }
            if (df.y < bd){ bd = df.y; bi = 2*(pbase + p) + 1; }
        }
        g_bd[h * NVEC + nq[q]] = bd;
        g_bi[h * NVEC + nq[q]] = bi;
    }

    // ---- per-chunk ticket: second CTA of the pair merges this chunk ----
    __threadfence();
    __syncthreads();
    if (tid == 0){
        unsigned old = atomicAdd(&g_ct[chunk], 1u);
        sMerge = (old == 1u);
        if (sMerge) g_ct[chunk] = 0;            // reset for next replay
    }
    __syncthreads();

    float lossLocal = 0.f;
    if (sMerge){
        __threadfence();                        // acquire both halves' writes
        float d0[QPT], d1[QPT];
        int   i0[QPT], i1[QPT];
        #pragma unroll
        for (int q = 0; q < QPT; q++){
            if (vq[q]){
                d0[q] = g_bd[nq[q]];
                d1[q] = g_bd[NVEC + nq[q]];
                i0[q] = g_bi[nq[q]];
                i1[q] = g_bi[NVEC + nq[q]];
            }
        }
        #pragma unroll
        for (int q = 0; q < QPT; q++){
            if (!vq[q]) continue;
            // strict <: half 0 (lower indices) wins ties -> first-occurrence
            const bool take1 = d1[q] < d0[q];
            const float d  = take1 ? d1[q] : d0[q];
            const int   bi = take1 ? i1[q] : i0[q];
            lossLocal += d;                     // sum((e-z)^2) == dist (R10-validated)

            const int b = nq[q] >> 15;
            const int s = nq[q] & (SP - 1);
            const float4* e4 = reinterpret_cast<const float4*>(emb + (size_t)bi * EDIM);
            const float4 ea = e4[0];
            const float4 eb = e4[1];
            float* o = out + (size_t)b * (EDIM * SP) + s;
            o[0 * SP] = ea.x; o[1 * SP] = ea.y; o[2 * SP] = ea.z; o[3 * SP] = ea.w;
            o[4 * SP] = eb.x; o[5 * SP] = eb.y; o[6 * SP] = eb.z; o[7 * SP] = eb.w;

            out[NZ + 2 + nq[q]] = (float)bi;
            g_used[bi] = 1;
        }

        // chunk loss partial (fixed order: warp shuffle + warp sums)
        #pragma unroll
        for (int o = 16; o > 0; o >>= 1)
            lossLocal += __shfl_down_sync(0xffffffffu, lossLocal, o);
        const int lane = tid & 31, w = tid >> 5;
        if (lane == 0) sRed[w] = lossLocal;
        __syncthreads();
        if (tid == 0){
            float v = 0.f;
            #pragma unroll
            for (int i = 0; i < THREADS / 32; i++) v += sRed[i];
            g_partial[chunk] = v;
        }
    }

    // ---- global ticket: last CTA finalizes loss scalar + unique ----
    __threadfence();
    __syncthreads();
    if (tid == 0){
        unsigned old = atomicAdd(&g_ticket, 1u);
        sLast = (old == (unsigned)(nctas - 1));
    }
    __syncthreads();

    if (sLast){
        __threadfence();
        int cnt = 0;
        for (int i = tid; i < NCODES; i += THREADS){
            cnt += (g_used[i] != 0);
            g_used[i] = 0;                      // reset for next replay
        }
        float s = 0.f;
        for (int i = tid; i < NCHUNK; i += THREADS) s += g_partial[i];

        #pragma unroll
        for (int o = 16; o > 0; o >>= 1){
            s   += __shfl_down_sync(0xffffffffu, s, o);
            cnt += __shfl_down_sync(0xffffffffu, cnt, o);
        }
        const int lane = tid & 31, w = tid >> 5;
        __shared__ float rs[THREADS / 32];
        __shared__ int   rc[THREADS / 32];
        if (lane == 0){ rs[w] = s; rc[w] = cnt; }
        __syncthreads();
        if (tid == 0){
            float total = 0.f; int ctotal = 0;
            #pragma unroll
            for (int i = 0; i < THREADS / 32; i++){ total += rs[i]; ctotal += rc[i]; }
            // loss = beta*mean + mean = 1.25 * sum / NZ
            out[NZ]     = 1.25f * total / (float)NZ;
            out[NZ + 1] = (float)ctotal;
            __threadfence();
            g_ticket = 0;                       // reset for next graph replay
        }
    }
}

extern "C" void kernel_launch(void* const* d_in, const int* in_sizes, int n_in,
                              void* d_out, int out_size)
{
    const float* z   = (const float*)d_in[0];
    const float* emb = (const float*)d_in[1];
    float* out = (float*)d_out;

    const int nctas = NCHUNK * 2;     // 1366 CTAs (683 chunks x 2 codebook halves)
    vq_main<<<nctas, THREADS>>>(z, emb, out, nctas);
}

// round 14
// speedup vs baseline: 1.1302x; 1.1302x over previous
#include <cuda_runtime.h>
#include <cstdint>

#define EDIM    8
#define NCODES  1024
#define HPAIR   256          // pairs per codebook half
#define SP      32768        // 32*32*32 spatial per batch
#define THREADS 128
#define QPT     4            // queries per thread
#define NVEC    262144
#define NZ      (NVEC * EDIM)
#define NCHUNK  512          // query chunks
#define NITEMS  (2 * NCHUNK) // (chunk, half) work items
#define GRID    760          // persistent CTAs (= 5/SM residency)

typedef unsigned long long ull;

// ---- device scratch (no allocations; self-resetting across graph replays) ----
__device__ float    g_bd[2 * NVEC];    // best dist per (half, query)
__device__ int      g_bi[2 * NVEC];    // best code idx per (half, query)
__device__ float    g_partial[NCHUNK]; // per-chunk loss partials
__device__ int      g_used[NCODES];    // set by merger, counted+reset by finalizer
__device__ unsigned g_ct[NCHUNK];      // per-chunk tickets (merger resets)
__device__ unsigned g_next = 0;        // dynamic work counter (finalizer resets)
__device__ unsigned g_ticket = 0;      // global ticket; finalizer resets

// ---- packed f32x2 helpers (Blackwell FFMA2 path, PTX-only) ----
__device__ __forceinline__ ull pack2(float lo, float hi){
    ull d;
    asm("mov.b64 %0, {%1, %2};" : "=l"(d)
        : "r"(__float_as_uint(lo)), "r"(__float_as_uint(hi)));
    return d;
}
__device__ __forceinline__ ull fma2(ull a, ull b, ull c){
    ull d; asm("fma.rn.f32x2 %0, %1, %2, %3;" : "=l"(d) : "l"(a), "l"(b), "l"(c));
    return d;
}
__device__ __forceinline__ ull mul2(ull a, ull b){
    ull d; asm("mul.rn.f32x2 %0, %1, %2;" : "=l"(d) : "l"(a), "l"(b));
    return d;
}
__device__ __forceinline__ ull add2(ull a, ull b){
    ull d; asm("add.rn.f32x2 %0, %1, %2;" : "=l"(d) : "l"(a), "l"(b));
    return d;
}
union U64F2 { ull u; float2 f; };
__device__ __forceinline__ float2 asf2(ull v){ U64F2 x; x.u = v; return x.f; }

// Bit-exact pair distance: d_pair = fma2(dot2, {-2,-2}, add2(ee2, zz2))
// (this exact op structure reproduces the reference's rounding; do not change)
__device__ __forceinline__ ull pair_dist(const ulonglong2* ep, ull eep,
                                         const ull* zp, ull zzp, ull m2){
    const ulonglong2 e01 = ep[0];
    const ulonglong2 e23 = ep[1];
    const ulonglong2 e45 = ep[2];
    const ulonglong2 e67 = ep[3];
    ull a = mul2(zp[0], e01.x);
    a = fma2(zp[1], e01.y, a);
    a = fma2(zp[2], e23.x, a);
    a = fma2(zp[3], e23.y, a);
    a = fma2(zp[4], e45.x, a);
    a = fma2(zp[5], e45.y, a);
    a = fma2(zp[6], e67.x, a);
    a = fma2(zp[7], e67.y, a);
    return fma2(a, m2, add2(eep, zzp));
}

// ---- persistent kernel: dynamic items -> search + chunk merge + finalize ----
__global__ __launch_bounds__(THREADS, 5) void vq_main(
    const float* __restrict__ z,
    const float* __restrict__ emb,
    float* __restrict__ out)
{
    __shared__ __align__(16) float2 sE[HPAIR * EDIM];  // half codebook, 16KB
    __shared__ __align__(16) float  sEE[HPAIR * 2];    // half norms, 2KB
    __shared__ float sRed[THREADS / 32];
    __shared__ bool  sMerge, sLast;
    __shared__ int   sItem;

    const int tid = threadIdx.x;
    int hPrev = -1;

    for (;;){
        __syncthreads();                       // protect sItem / sE reuse
        if (tid == 0) sItem = (int)atomicAdd(&g_next, 1u);
        __syncthreads();
        const int item = sItem;
        if (item >= NITEMS) break;

        const int h     = item >> 9;           // half-major: 0..511 h0, 512.. h1
        const int chunk = item & (NCHUNK - 1);
        const int pbase = h * HPAIR;

        if (h != hPrev){
            // Stage this half's codebook: float4 loads, norms fused.
            #pragma unroll
            for (int r = 0; r < 2; r++){
                const int p = tid + r * THREADS;         // local pair 0..255
                const int P = pbase + p;
                const float4* c4 = reinterpret_cast<const float4*>(emb + (size_t)(2*P) * EDIM);
                const float4 a0 = c4[0], a1 = c4[1];     // code 2P
                const float4 b0 = c4[2], b1 = c4[3];     // code 2P+1
                float2* se = sE + p * EDIM;
                se[0] = make_float2(a0.x, b0.x); se[1] = make_float2(a0.y, b0.y);
                se[2] = make_float2(a0.z, b0.z); se[3] = make_float2(a0.w, b0.w);
                se[4] = make_float2(a1.x, b1.x); se[5] = make_float2(a1.y, b1.y);
                se[6] = make_float2(a1.z, b1.z); se[7] = make_float2(a1.w, b1.w);
                float sa = a0.x*a0.x; sa = fmaf(a0.y,a0.y,sa); sa = fmaf(a0.z,a0.z,sa);
                sa = fmaf(a0.w,a0.w,sa); sa = fmaf(a1.x,a1.x,sa); sa = fmaf(a1.y,a1.y,sa);
                sa = fmaf(a1.z,a1.z,sa); sa = fmaf(a1.w,a1.w,sa);
                float sb = b0.x*b0.x; sb = fmaf(b0.y,b0.y,sb); sb = fmaf(b0.z,b0.z,sb);
                sb = fmaf(b0.w,b0.w,sb); sb = fmaf(b1.x,b1.x,sb); sb = fmaf(b1.y,b1.y,sb);
                sb = fmaf(b1.z,b1.z,sb); sb = fmaf(b1.w,b1.w,sb);
                sEE[2*p]   = sa;
                sEE[2*p+1] = sb;
            }
            hPrev = h;
        }
        __syncthreads();

        // Interleaved query mapping (coalesced): nq = t + q*part
        const int part = NVEC / QPT;           // 65536
        const int t = chunk * THREADS + tid;

        int nq[QPT];
        ull zp[QPT][EDIM];
        ull zzp[QPT];

        #pragma unroll
        for (int q = 0; q < QPT; q++){
            nq[q] = t + q * part;
            const int b = nq[q] >> 15;
            const int s = nq[q] & (SP - 1);
            const float* zptr = z + (size_t)b * (EDIM * SP) + s;
            float zz = 0.f;
            #pragma unroll
            for (int c = 0; c < EDIM; c++){
                float v = zptr[c * SP];
                zp[q][c] = pack2(v, v);
                zz = fmaf(v, v, zz);
            }
            zzp[q] = pack2(zz, zz);
        }
        const ull m2 = pack2(-2.f, -2.f);

        float best[QPT];
        int   bgp[QPT];                        // winning LOCAL group base pair (even)
        #pragma unroll
        for (int q = 0; q < QPT; q++){ best[q] = 3.4e38f; bgp[q] = 0; }

        // Group of 2 pairs per step; codebook loads amortized over 4 queries.
        for (int p = 0; p < HPAIR; p += 2){
            const ulonglong2* epA = reinterpret_cast<const ulonglong2*>(sE + p * EDIM);
            const ulonglong2* epB = reinterpret_cast<const ulonglong2*>(sE + (p + 1) * EDIM);
            const ulonglong2 eeAB = *reinterpret_cast<const ulonglong2*>(sEE + 2 * p);

            float2 dA0 = asf2(pair_dist(epA, eeAB.x, zp[0], zzp[0], m2));
            float2 dA1 = asf2(pair_dist(epA, eeAB.x, zp[1], zzp[1], m2));
            float2 dA2 = asf2(pair_dist(epA, eeAB.x, zp[2], zzp[2], m2));
            float2 dA3 = asf2(pair_dist(epA, eeAB.x, zp[3], zzp[3], m2));
            float2 dB0 = asf2(pair_dist(epB, eeAB.y, zp[0], zzp[0], m2));
            float2 dB1 = asf2(pair_dist(epB, eeAB.y, zp[1], zzp[1], m2));
            float2 dB2 = asf2(pair_dist(epB, eeAB.y, zp[2], zzp[2], m2));
            float2 dB3 = asf2(pair_dist(epB, eeAB.y, zp[3], zzp[3], m2));

            {
                float gm = fminf(fminf(dA0.x, dA0.y), fminf(dB0.x, dB0.y));
                bool u = gm < best[0]; bgp[0] = u ? p : bgp[0]; best[0] = fminf(best[0], gm);
            }
            {
                float gm = fminf(fminf(dA1.x, dA1.y), fminf(dB1.x, dB1.y));
                bool u = gm < best[1]; bgp[1] = u ? p : bgp[1]; best[1] = fminf(best[1], gm);
            }
            {
                float gm = fminf(fminf(dA2.x, dA2.y), fminf(dB2.x, dB2.y));
                bool u = gm < best[2]; bgp[2] = u ? p : bgp[2]; best[2] = fminf(best[2], gm);
            }
            {
                float gm = fminf(fminf(dA3.x, dA3.y), fminf(dB3.x, dB3.y));
                bool u = gm < best[3]; bgp[3] = u ? p : bgp[3]; best[3] = fminf(best[3], gm);
            }
        }

        // Rescan winning 2-pair group (bit-exact), first-occurrence argmin; store.
        #pragma unroll
        for (int q = 0; q < QPT; q++){
            const int gp = bgp[q];
            float bd = 3.4e38f;
            int bi = 0;
            #pragma unroll
            for (int j = 0; j < 2; j++){
                const int p = gp + j;
                const ulonglong2* ep = reinterpret_cast<const ulonglong2*>(sE + p * EDIM);
                const ull eep = *reinterpret_cast<const ull*>(sEE + 2 * p);
                float2 df = asf2(pair_dist(ep, eep, zp[q], zzp[q], m2));
                if (df.x < bd){ bd = df.x; bi = 2*(pbase + p); }
                if (df.y < bd){ bd = df.y; bi = 2*(pbase + p) + 1; }
            }
            g_bd[h * NVEC + nq[q]] = bd;
            g_bi[h * NVEC + nq[q]] = bi;
        }

        // ---- per-chunk ticket: second half to finish merges this chunk ----
        __threadfence();
        __syncthreads();
        if (tid == 0){
            unsigned old = atomicAdd(&g_ct[chunk], 1u);
            sMerge = (old == 1u);
            if (sMerge) g_ct[chunk] = 0;        // reset for next replay
        }
        __syncthreads();

        if (sMerge){
            __threadfence();                    // acquire both halves' writes
            float lossLocal = 0.f;
            float d0[QPT], d1[QPT];
            int   i0[QPT], i1[QPT];
            #pragma unroll
            for (int q = 0; q < QPT; q++){
                d0[q] = g_bd[nq[q]];
                d1[q] = g_bd[NVEC + nq[q]];
                i0[q] = g_bi[nq[q]];
                i1[q] = g_bi[NVEC + nq[q]];
            }
            #pragma unroll
            for (int q = 0; q < QPT; q++){
                // strict <: half 0 (lower indices) wins ties -> first-occurrence
                const bool take1 = d1[q] < d0[q];
                const float d  = take1 ? d1[q] : d0[q];
                const int   bi = take1 ? i1[q] : i0[q];
                lossLocal += d;                 // sum((e-z)^2) == dist (R10-validated)

                const int b = nq[q] >> 15;
                const int s = nq[q] & (SP - 1);
                const float4* e4 = reinterpret_cast<const float4*>(emb + (size_t)bi * EDIM);
                const float4 ea = e4[0];
                const float4 eb = e4[1];
                float* o = out + (size_t)b * (EDIM * SP) + s;
                o[0 * SP] = ea.x; o[1 * SP] = ea.y; o[2 * SP] = ea.z; o[3 * SP] = ea.w;
                o[4 * SP] = eb.x; o[5 * SP] = eb.y; o[6 * SP] = eb.z; o[7 * SP] = eb.w;

                out[NZ + 2 + nq[q]] = (float)bi;
                g_used[bi] = 1;
            }

            // chunk loss partial (fixed order)
            #pragma unroll
            for (int o = 16; o > 0; o >>= 1)
                lossLocal += __shfl_down_sync(0xffffffffu, lossLocal, o);
            const int lane = tid & 31, w = tid >> 5;
            if (lane == 0) sRed[w] = lossLocal;
            __syncthreads();
            if (tid == 0){
                float v = 0.f;
                #pragma unroll
                for (int i = 0; i < THREADS / 32; i++) v += sRed[i];
                g_partial[chunk] = v;
            }
        }
    }

    // ---- global ticket: last CTA finalizes loss scalar + unique ----
    __threadfence();
    if (tid == 0){
        unsigned old = atomicAdd(&g_ticket, 1u);
        sLast = (old == (unsigned)(GRID - 1));
    }
    __syncthreads();

    if (sLast){
        __threadfence();
        int cnt = 0;
        for (int i = tid; i < NCODES; i += THREADS){
            cnt += (g_used[i] != 0);
            g_used[i] = 0;                      // reset for next replay
        }
        float s = 0.f;
        for (int i = tid; i < NCHUNK; i += THREADS) s += g_partial[i];

        #pragma unroll
        for (int o = 16; o > 0; o >>= 1){
            s   += __shfl_down_sync(0xffffffffu, s, o);
            cnt += __shfl_down_sync(0xffffffffu, cnt, o);
        }
        const int lane = tid & 31, w = tid >> 5;
        __shared__ float rs[THREADS / 32];
        __shared__ int   rc[THREADS / 32];
        if (lane == 0){ rs[w] = s; rc[w] = cnt; }
        __syncthreads();
        if (tid == 0){
            float total = 0.f; int ctotal = 0;
            #pragma unroll
            for (int i = 0; i < THREADS / 32; i++){ total += rs[i]; ctotal += rc[i]; }
            // loss = beta*mean + mean = 1.25 * sum / NZ
            out[NZ]     = 1.25f * total / (float)NZ;
            out[NZ + 1] = (float)ctotal;
            __threadfence();
            g_ticket = 0;                       // reset for next graph replay
            g_next   = 0;
        }
    }
}

extern "C" void kernel_launch(void* const* d_in, const int* in_sizes, int n_in,
                              void* d_out, int out_size)
{
    const float* z   = (const float*)d_in[0];
    const float* emb = (const float*)d_in[1];
    float* out = (float*)d_out;

    vq_main<<<GRID, THREADS>>>(z, emb, out);
}